// round 13
// baseline (speedup 1.0000x reference)
#include <cuda_runtime.h>
#include <cuda_fp16.h>
#include <cstdint>

#define N_ROWS 8192
#define IN_F   2048
#define OUT_F  2048
#define XN     512
#define NPROD  8

static constexpr size_t NT = (size_t)N_ROWS * XN;

// ---------------- static device scratch ----------------
__device__ __half g_xc[NPROD * NT];          // 8 X-combos [8192 x 512] fp16 (64 MB)
__device__ __half g_wt[NPROD * XN * XN];     // 8 W-combos [512 x 512] fp16, [nu][kappa]
__device__ __half g_t [NPROD * NT];          // 8 products [8192 x 512] fp16 (64 MB)

// ---------------- prep: X combos (8 elements / thread, 16B stores) ----------
__global__ void make_xc_kernel(const float* __restrict__ in) {
    size_t i = (size_t)blockIdx.x * blockDim.x + threadIdx.x;   // octet index
    if (i >= NT / 8) return;
    size_t base = i * 8;
    float4 v[8];
#pragma unroll
    for (int j = 0; j < 8; ++j) v[j] = reinterpret_cast<const float4*>(in)[base + j];

#define PUTP(p, EXPR)                                                              \
    {                                                                              \
        uint4 o;                                                                   \
        uint32_t* op = reinterpret_cast<uint32_t*>(&o);                            \
        _Pragma("unroll")                                                          \
        for (int j = 0; j < 4; ++j) {                                              \
            float4 a = v[2 * j], b = v[2 * j + 1];                                 \
            __half2 h = __floats2half2_rn((EXPR(a)), (EXPR(b)));                   \
            op[j] = reinterpret_cast<uint32_t&>(h);                                \
        }                                                                          \
        *reinterpret_cast<uint4*>(&g_xc[(size_t)(p) * NT + base]) = o;             \
    }
#define E0(q) ((q).x + (q).y)
#define E1(q) ((q).z - (q).w)
#define E2(q) ((q).z + (q).w)
#define E3(q) ((q).x - (q).y)
#define E4(q) ((q).y + (q).z)
#define E5(q) ((q).y - (q).z)
#define E6(q) ((q).x - (q).w)
#define E7(q) ((q).x + (q).w)
    PUTP(0, E0) PUTP(1, E1) PUTP(2, E2) PUTP(3, E3)
    PUTP(4, E4) PUTP(5, E5) PUTP(6, E6) PUTP(7, E7)
#undef PUTP
#undef E0
#undef E1
#undef E2
#undef E3
#undef E4
#undef E5
#undef E6
#undef E7
}

// ---------------- prep: W combos (transposed to [nu][kappa]) ----------------
__global__ void make_wc_kernel(const float* __restrict__ w) {
    __shared__ __half tile[NPROD][32][33];
    const int kap0 = blockIdx.x * 32;
    const int nu0  = blockIdx.y * 32;
    const int tid = threadIdx.x;
    for (int p = 0; p < 4; ++p) {
        int r = p * 8 + (tid >> 5);
        int cnu = tid & 31;
        const float* wr = w + (size_t)(kap0 + r) * OUT_F + nu0 + cnu;
        float b0 = wr[0], b1 = wr[512], b2 = wr[1024], b3 = wr[1536];
        tile[0][r][cnu] = __float2half_rn(b0 - b1);
        tile[1][r][cnu] = __float2half_rn(b2 - b3);
        tile[2][r][cnu] = __float2half_rn(b0 + b1);
        tile[3][r][cnu] = __float2half_rn(b2 + b3);
        tile[4][r][cnu] = __float2half_rn(0.5f * (b1 + b3));
        tile[5][r][cnu] = __float2half_rn(0.5f * (b1 - b3));
        tile[6][r][cnu] = __float2half_rn(0.5f * (b0 - b2));
        tile[7][r][cnu] = __float2half_rn(0.5f * (b0 + b2));
    }
    __syncthreads();
    for (int p = 0; p < 4; ++p) {
        int rnu = p * 8 + (tid >> 5);
        int ck  = tid & 31;
#pragma unroll
        for (int i = 0; i < NPROD; ++i) {
            g_wt[(size_t)i * XN * XN + (size_t)(nu0 + rnu) * XN + kap0 + ck] = tile[i][ck][rnu];
        }
    }
}

// ---------------- PTX helpers ----------------
__device__ __forceinline__ uint32_t smem_u32(const void* p) {
    uint32_t a;
    asm("{ .reg .u64 t; cvta.to.shared.u64 t, %1; cvt.u32.u64 %0, t; }" : "=r"(a) : "l"(p));
    return a;
}

#define CP_ASYNC16(dst, src) \
    asm volatile("cp.async.cg.shared.global [%0], [%1], 16;" :: "r"(dst), "l"(src))
#define CP_COMMIT() asm volatile("cp.async.commit_group;")
#define CP_WAIT(n)  asm volatile("cp.async.wait_group %0;" :: "n"(n))

__device__ __forceinline__ void ldsm_x4(uint32_t& r0, uint32_t& r1, uint32_t& r2, uint32_t& r3,
                                        uint32_t addr) {
    asm volatile("ldmatrix.sync.aligned.m8n8.x4.shared.b16 {%0,%1,%2,%3}, [%4];"
                 : "=r"(r0), "=r"(r1), "=r"(r2), "=r"(r3) : "r"(addr));
}

__device__ __forceinline__ void hmma(float* c, const uint32_t* a, uint32_t b0, uint32_t b1) {
    asm volatile(
        "mma.sync.aligned.m16n8k16.row.col.f32.f16.f16.f32 "
        "{%0,%1,%2,%3}, {%4,%5,%6,%7}, {%8,%9}, {%0,%1,%2,%3};"
        : "+f"(c[0]), "+f"(c[1]), "+f"(c[2]), "+f"(c[3])
        : "r"(a[0]), "r"(a[1]), "r"(a[2]), "r"(a[3]), "r"(b0), "r"(b1));
}

// ---------------- batched GEMM: t_z = XC_z [8192x512] @ WT_z [512x512]^T ----------------
#define BM 128
#define BN 128
#define BK 64
#define STAGES 3
#define THREADS 256
#define KTILES (XN / BK)      // 8

static constexpr int CHUNK_B = BM * 32 * 2;
static constexpr int OP_B    = 2 * CHUNK_B;
static constexpr int STAGE_B = 2 * OP_B;
static constexpr int SMEM_TOTAL = STAGES * STAGE_B;  // 96 KB

__global__ void __launch_bounds__(THREADS, 2) qprod_gemm()
{
    extern __shared__ char smem[];
    const uint32_t sbase = smem_u32(smem);
    const int tid  = threadIdx.x;
    const int wid  = tid >> 5;
    const int lane = tid & 31;
    const int warp_m = wid & 3;
    const int warp_n = wid >> 2;
    const int m0 = blockIdx.y * BM;
    const int n0 = blockIdx.x * BN;
    const int z  = blockIdx.z;

    const __half* gA = g_xc + (size_t)z * NT + (size_t)m0 * XN;
    const __half* gB = g_wt + (size_t)z * XN * XN + (size_t)n0 * XN;
    __half* gT = g_t + (size_t)z * NT;

    const int lr = tid >> 2;
    const int lc = tid & 3;
    const uint32_t dst_off = lr * 64 + ((lc ^ ((lr >> 1) & 3)) << 4);
    const size_t src_off = (size_t)lr * XN + lc * 8;

    const int g = lane >> 3, r = lane & 7;
    uint32_t a_row[2], a_sw[2];
    const int a_gbit = g >> 1;
#pragma unroll
    for (int mt = 0; mt < 2; ++mt) {
        int row = warp_m * 32 + mt * 16 + (g & 1) * 8 + r;
        a_row[mt] = row * 64;
        a_sw[mt]  = (row >> 1) & 3;
    }
    uint32_t b_row[4], b_sw[4];
    const int b_gbit = g & 1;
#pragma unroll
    for (int np = 0; np < 4; ++np) {
        int row = warp_n * 64 + np * 16 + (g >> 1) * 8 + r;
        b_row[np] = row * 64;
        b_sw[np]  = (row >> 1) & 3;
    }

    float acc[2][8][4];
#pragma unroll
    for (int mt = 0; mt < 2; ++mt)
#pragma unroll
        for (int nt = 0; nt < 8; ++nt)
#pragma unroll
            for (int e = 0; e < 4; ++e) acc[mt][nt][e] = 0.0f;

    int slot_of[KTILES + STAGES];
#pragma unroll
    for (int s = 0; s < KTILES + STAGES; ++s) slot_of[s] = s % STAGES;

    auto load_stage = [&](int s) {
        const int kc = s * BK;
        const uint32_t sb = sbase + slot_of[s] * STAGE_B;
        {
            const __half* asrc = gA + kc + src_off;
            const __half* bsrc = gB + kc + src_off;
#pragma unroll
            for (int c = 0; c < 2; ++c) {
                uint32_t da = sb + c * CHUNK_B + dst_off;
                uint32_t db = sb + OP_B + c * CHUNK_B + dst_off;
                CP_ASYNC16(da,        asrc + c * 32);
                CP_ASYNC16(da + 4096, asrc + c * 32 + (size_t)64 * XN);
                CP_ASYNC16(db,        bsrc + c * 32);
                CP_ASYNC16(db + 4096, bsrc + c * 32 + (size_t)64 * XN);
            }
        }
    };

    load_stage(0); CP_COMMIT();
    load_stage(1); CP_COMMIT();

    for (int s = 0; s < KTILES; ++s) {
        CP_WAIT(1);
        __syncthreads();
        if (s + 2 < KTILES) load_stage(s + 2);
        CP_COMMIT();

        const uint32_t sb = sbase + slot_of[s] * STAGE_B;
#pragma unroll
        for (int sk = 0; sk < 4; ++sk) {
            const uint32_t abase = sb + (sk >> 1) * CHUNK_B;
            const uint32_t bbase = sb + OP_B + (sk >> 1) * CHUNK_B;
            const uint32_t ca = (uint32_t)(2 * (sk & 1) + a_gbit);
            const uint32_t cb = (uint32_t)(2 * (sk & 1) + b_gbit);
            uint32_t ah[2][4], bh[4][4];
#pragma unroll
            for (int mt = 0; mt < 2; ++mt) {
                uint32_t off = a_row[mt] + ((ca ^ a_sw[mt]) << 4);
                ldsm_x4(ah[mt][0], ah[mt][1], ah[mt][2], ah[mt][3], abase + off);
            }
#pragma unroll
            for (int np = 0; np < 4; ++np) {
                uint32_t off = b_row[np] + ((cb ^ b_sw[np]) << 4);
                ldsm_x4(bh[np][0], bh[np][1], bh[np][2], bh[np][3], bbase + off);
            }
#pragma unroll
            for (int mt = 0; mt < 2; ++mt) {
#pragma unroll
                for (int nt = 0; nt < 8; ++nt) {
                    const int np = nt >> 1, sel = (nt & 1) * 2;
                    hmma(acc[mt][nt], ah[mt], bh[np][sel], bh[np][sel + 1]);
                }
            }
        }
    }

    // ---- epilogue: store t (fp16, pitch 512) ----
#pragma unroll
    for (int mt = 0; mt < 2; ++mt) {
        int row = m0 + warp_m * 32 + mt * 16 + (lane >> 2);
#pragma unroll
        for (int nt = 0; nt < 8; ++nt) {
            int col = n0 + warp_n * 64 + nt * 8 + (lane & 3) * 2;
            *reinterpret_cast<__half2*>(gT + (size_t)row * XN + col) =
                __floats2half2_rn(acc[mt][nt][0], acc[mt][nt][1]);
            *reinterpret_cast<__half2*>(gT + (size_t)(row + 8) * XN + col) =
                __floats2half2_rn(acc[mt][nt][2], acc[mt][nt][3]);
        }
    }
}

// ---------------- combine: 16B/plane loads, 8 outputs per thread ----------
// O0 = T1 + (T4+T5) + (T6+T7)
// O1 = T0 + (T4+T5) - (T6+T7)
// O2 = T2 - (T4-T5) + (T6-T7)
// O3 = -T3 - (T4-T5) - (T6-T7)
__global__ void combine_kernel(const float* __restrict__ bias, float* __restrict__ out) {
    size_t i = (size_t)blockIdx.x * blockDim.x + threadIdx.x;   // octet index
    if (i >= NT / 8) return;
    size_t base = i * 8;
    uint4 tp[8];
#pragma unroll
    for (int p = 0; p < 8; ++p)
        tp[p] = *reinterpret_cast<const uint4*>(&g_t[(size_t)p * NT + base]);

    int nu = (int)(base & 511);
    const float4* bias4 = reinterpret_cast<const float4*>(bias);
    float4* out4 = reinterpret_cast<float4*>(out);

#pragma unroll
    for (int c = 0; c < 4; ++c) {         // half2 chunk
        float2 t[8];
#pragma unroll
        for (int p = 0; p < 8; ++p) {
            uint32_t u = reinterpret_cast<const uint32_t*>(&tp[p])[c];
            t[p] = __half22float2(reinterpret_cast<__half2&>(u));
        }
#pragma unroll
        for (int j = 0; j < 2; ++j) {
            float t0 = j ? t[0].y : t[0].x, t1 = j ? t[1].y : t[1].x;
            float t2 = j ? t[2].y : t[2].x, t3 = j ? t[3].y : t[3].x;
            float t4 = j ? t[4].y : t[4].x, t5 = j ? t[5].y : t[5].x;
            float t6 = j ? t[6].y : t[6].x, t7 = j ? t[7].y : t[7].x;
            float s1 = t4 + t5, s2 = t6 + t7;
            float d1 = t4 - t5, d2 = t6 - t7;
            float4 b = bias4[nu + 2 * c + j];
            float4 o;
            o.x =  t1 + s1 + s2 + b.x;
            o.y =  t0 + s1 - s2 + b.y;
            o.z =  t2 - d1 + d2 + b.z;
            o.w = -t3 - d1 - d2 + b.w;
            out4[base + 2 * c + j] = o;
        }
    }
}

// ---------------- launch ----------------
extern "C" void kernel_launch(void* const* d_in, const int* in_sizes, int n_in,
                              void* d_out, int out_size) {
    (void)in_sizes; (void)n_in; (void)out_size;
    const float* input  = (const float*)d_in[0];
    const float* weight = (const float*)d_in[1];
    const float* bias   = (const float*)d_in[2];
    float* out = (float*)d_out;

    cudaFuncSetAttribute(qprod_gemm, cudaFuncAttributeMaxDynamicSharedMemorySize, SMEM_TOTAL);

    make_xc_kernel<<<(unsigned)((NT / 8 + 255) / 256), 256>>>(input);
    make_wc_kernel<<<dim3(XN / 32, XN / 32), 256>>>(weight);
    qprod_gemm<<<dim3(XN / BN, N_ROWS / BM, NPROD), THREADS, SMEM_TOTAL>>>();
    combine_kernel<<<(unsigned)((NT / 8 + 255) / 256), 256>>>(bias, out);
}

// round 14
// speedup vs baseline: 1.1449x; 1.1449x over previous
#include <cuda_runtime.h>
#include <cuda_fp16.h>
#include <cstdint>

#define N_ROWS 8192
#define IN_F   2048
#define OUT_F  2048
#define XN     512
#define NPROD  8

static constexpr size_t NT = (size_t)N_ROWS * XN;

// ---------------- static device scratch ----------------
__device__ __half g_xc[NPROD * NT];          // 8 X-combos [8192 x 512] fp16 (64 MB)
__device__ __half g_wt[NPROD * XN * XN];     // 8 W-combos [512 x 512] fp16, [nu][kappa]
__device__ __half g_t [NPROD * NT];          // 8 products [8192 x 512] fp16 (64 MB)

// ---------------- fused prep: X combos (blocks 0..8191) + W combos (8192..8447)
#define XC_BLOCKS 8192

__global__ void prep_kernel(const float* __restrict__ in, const float* __restrict__ w) {
    __shared__ __half tile[NPROD][32][33];
    const int tid = threadIdx.x;
    if (blockIdx.x < XC_BLOCKS) {
        // ---- X combos: 2 elements per thread, half2 stores ----
        size_t i = (size_t)blockIdx.x * blockDim.x + tid;   // pair index
        if (i >= NT / 2) return;
        size_t i2 = i * 2;
        float4 v0 = reinterpret_cast<const float4*>(in)[i2];
        float4 v1 = reinterpret_cast<const float4*>(in)[i2 + 1];
#define PUT(p, e0, e1) \
        *reinterpret_cast<__half2*>(&g_xc[(size_t)(p) * NT + i2]) = __floats2half2_rn(e0, e1)
        PUT(0, v0.x + v0.y, v1.x + v1.y);
        PUT(1, v0.z - v0.w, v1.z - v1.w);
        PUT(2, v0.z + v0.w, v1.z + v1.w);
        PUT(3, v0.x - v0.y, v1.x - v1.y);
        PUT(4, v0.y + v0.z, v1.y + v1.z);
        PUT(5, v0.y - v0.z, v1.y - v1.z);
        PUT(6, v0.x - v0.w, v1.x - v1.w);
        PUT(7, v0.x + v0.w, v1.x + v1.w);
#undef PUT
    } else {
        // ---- W combos: 32x32 transpose tiles ----
        const int bid = blockIdx.x - XC_BLOCKS;       // 0..255
        const int kap0 = (bid >> 4) * 32;
        const int nu0  = (bid & 15) * 32;
        for (int p = 0; p < 4; ++p) {
            int r = p * 8 + (tid >> 5);
            int cnu = tid & 31;
            const float* wr = w + (size_t)(kap0 + r) * OUT_F + nu0 + cnu;
            float b0 = wr[0], b1 = wr[512], b2 = wr[1024], b3 = wr[1536];
            tile[0][r][cnu] = __float2half_rn(b0 - b1);
            tile[1][r][cnu] = __float2half_rn(b2 - b3);
            tile[2][r][cnu] = __float2half_rn(b0 + b1);
            tile[3][r][cnu] = __float2half_rn(b2 + b3);
            tile[4][r][cnu] = __float2half_rn(0.5f * (b1 + b3));
            tile[5][r][cnu] = __float2half_rn(0.5f * (b1 - b3));
            tile[6][r][cnu] = __float2half_rn(0.5f * (b0 - b2));
            tile[7][r][cnu] = __float2half_rn(0.5f * (b0 + b2));
        }
        __syncthreads();
        for (int p = 0; p < 4; ++p) {
            int rnu = p * 8 + (tid >> 5);
            int ck  = tid & 31;
#pragma unroll
            for (int i = 0; i < NPROD; ++i) {
                g_wt[(size_t)i * XN * XN + (size_t)(nu0 + rnu) * XN + kap0 + ck] = tile[i][ck][rnu];
            }
        }
    }
}

// ---------------- PTX helpers ----------------
__device__ __forceinline__ uint32_t smem_u32(const void* p) {
    uint32_t a;
    asm("{ .reg .u64 t; cvta.to.shared.u64 t, %1; cvt.u32.u64 %0, t; }" : "=r"(a) : "l"(p));
    return a;
}

#define CP_ASYNC16(dst, src) \
    asm volatile("cp.async.cg.shared.global [%0], [%1], 16;" :: "r"(dst), "l"(src))
#define CP_COMMIT() asm volatile("cp.async.commit_group;")
#define CP_WAIT(n)  asm volatile("cp.async.wait_group %0;" :: "n"(n))

__device__ __forceinline__ void ldsm_x4(uint32_t& r0, uint32_t& r1, uint32_t& r2, uint32_t& r3,
                                        uint32_t addr) {
    asm volatile("ldmatrix.sync.aligned.m8n8.x4.shared.b16 {%0,%1,%2,%3}, [%4];"
                 : "=r"(r0), "=r"(r1), "=r"(r2), "=r"(r3) : "r"(addr));
}

__device__ __forceinline__ void hmma(float* c, const uint32_t* a, uint32_t b0, uint32_t b1) {
    asm volatile(
        "mma.sync.aligned.m16n8k16.row.col.f32.f16.f16.f32 "
        "{%0,%1,%2,%3}, {%4,%5,%6,%7}, {%8,%9}, {%0,%1,%2,%3};"
        : "+f"(c[0]), "+f"(c[1]), "+f"(c[2]), "+f"(c[3])
        : "r"(a[0]), "r"(a[1]), "r"(a[2]), "r"(a[3]), "r"(b0), "r"(b1));
}

// ---------------- batched GEMM: t_z = XC_z [8192x512] @ WT_z [512x512]^T ----------------
#define BM 128
#define BN 128
#define BK 64
#define STAGES 3
#define THREADS 256
#define KTILES (XN / BK)      // 8

static constexpr int CHUNK_B = BM * 32 * 2;
static constexpr int OP_B    = 2 * CHUNK_B;
static constexpr int STAGE_B = 2 * OP_B;
static constexpr int SMEM_TOTAL = STAGES * STAGE_B;  // 96 KB

__global__ void __launch_bounds__(THREADS, 2) qprod_gemm()
{
    extern __shared__ char smem[];
    const uint32_t sbase = smem_u32(smem);
    const int tid  = threadIdx.x;
    const int wid  = tid >> 5;
    const int lane = tid & 31;
    const int warp_m = wid & 3;
    const int warp_n = wid >> 2;
    const int m0 = blockIdx.y * BM;
    const int n0 = blockIdx.x * BN;
    const int z  = blockIdx.z;

    const __half* gA = g_xc + (size_t)z * NT + (size_t)m0 * XN;
    const __half* gB = g_wt + (size_t)z * XN * XN + (size_t)n0 * XN;
    __half* gT = g_t + (size_t)z * NT;

    const int lr = tid >> 2;
    const int lc = tid & 3;
    const uint32_t dst_off = lr * 64 + ((lc ^ ((lr >> 1) & 3)) << 4);
    const size_t src_off = (size_t)lr * XN + lc * 8;

    const int g = lane >> 3, r = lane & 7;
    uint32_t a_row[2], a_sw[2];
    const int a_gbit = g >> 1;
#pragma unroll
    for (int mt = 0; mt < 2; ++mt) {
        int row = warp_m * 32 + mt * 16 + (g & 1) * 8 + r;
        a_row[mt] = row * 64;
        a_sw[mt]  = (row >> 1) & 3;
    }
    uint32_t b_row[4], b_sw[4];
    const int b_gbit = g & 1;
#pragma unroll
    for (int np = 0; np < 4; ++np) {
        int row = warp_n * 64 + np * 16 + (g >> 1) * 8 + r;
        b_row[np] = row * 64;
        b_sw[np]  = (row >> 1) & 3;
    }

    float acc[2][8][4];
#pragma unroll
    for (int mt = 0; mt < 2; ++mt)
#pragma unroll
        for (int nt = 0; nt < 8; ++nt)
#pragma unroll
            for (int e = 0; e < 4; ++e) acc[mt][nt][e] = 0.0f;

    int slot_of[KTILES + STAGES];
#pragma unroll
    for (int s = 0; s < KTILES + STAGES; ++s) slot_of[s] = s % STAGES;

    auto load_stage = [&](int s) {
        const int kc = s * BK;
        const uint32_t sb = sbase + slot_of[s] * STAGE_B;
        {
            const __half* asrc = gA + kc + src_off;
            const __half* bsrc = gB + kc + src_off;
#pragma unroll
            for (int c = 0; c < 2; ++c) {
                uint32_t da = sb + c * CHUNK_B + dst_off;
                uint32_t db = sb + OP_B + c * CHUNK_B + dst_off;
                CP_ASYNC16(da,        asrc + c * 32);
                CP_ASYNC16(da + 4096, asrc + c * 32 + (size_t)64 * XN);
                CP_ASYNC16(db,        bsrc + c * 32);
                CP_ASYNC16(db + 4096, bsrc + c * 32 + (size_t)64 * XN);
            }
        }
    };

    load_stage(0); CP_COMMIT();
    load_stage(1); CP_COMMIT();

    for (int s = 0; s < KTILES; ++s) {
        CP_WAIT(1);
        __syncthreads();
        if (s + 2 < KTILES) load_stage(s + 2);
        CP_COMMIT();

        const uint32_t sb = sbase + slot_of[s] * STAGE_B;
#pragma unroll
        for (int sk = 0; sk < 4; ++sk) {
            const uint32_t abase = sb + (sk >> 1) * CHUNK_B;
            const uint32_t bbase = sb + OP_B + (sk >> 1) * CHUNK_B;
            const uint32_t ca = (uint32_t)(2 * (sk & 1) + a_gbit);
            const uint32_t cb = (uint32_t)(2 * (sk & 1) + b_gbit);
            uint32_t ah[2][4], bh[4][4];
#pragma unroll
            for (int mt = 0; mt < 2; ++mt) {
                uint32_t off = a_row[mt] + ((ca ^ a_sw[mt]) << 4);
                ldsm_x4(ah[mt][0], ah[mt][1], ah[mt][2], ah[mt][3], abase + off);
            }
#pragma unroll
            for (int np = 0; np < 4; ++np) {
                uint32_t off = b_row[np] + ((cb ^ b_sw[np]) << 4);
                ldsm_x4(bh[np][0], bh[np][1], bh[np][2], bh[np][3], bbase + off);
            }
#pragma unroll
            for (int mt = 0; mt < 2; ++mt) {
#pragma unroll
                for (int nt = 0; nt < 8; ++nt) {
                    const int np = nt >> 1, sel = (nt & 1) * 2;
                    hmma(acc[mt][nt], ah[mt], bh[np][sel], bh[np][sel + 1]);
                }
            }
        }
    }

    // ---- epilogue: store t (fp16, pitch 512) ----
#pragma unroll
    for (int mt = 0; mt < 2; ++mt) {
        int row = m0 + warp_m * 32 + mt * 16 + (lane >> 2);
#pragma unroll
        for (int nt = 0; nt < 8; ++nt) {
            int col = n0 + warp_n * 64 + nt * 8 + (lane & 3) * 2;
            *reinterpret_cast<__half2*>(gT + (size_t)row * XN + col) =
                __floats2half2_rn(acc[mt][nt][0], acc[mt][nt][1]);
            *reinterpret_cast<__half2*>(gT + (size_t)(row + 8) * XN + col) =
                __floats2half2_rn(acc[mt][nt][2], acc[mt][nt][3]);
        }
    }
}

// ---------------- combine: R12 shape + streaming cache hints ----------------
// O0 = T1 + (T4+T5) + (T6+T7)
// O1 = T0 + (T4+T5) - (T6+T7)
// O2 = T2 - (T4-T5) + (T6-T7)
// O3 = -T3 - (T4-T5) - (T6-T7)
__global__ void combine_kernel(const float* __restrict__ bias, float* __restrict__ out) {
    size_t i = (size_t)blockIdx.x * blockDim.x + threadIdx.x;   // pair index
    if (i >= NT / 2) return;
    size_t i2 = i * 2;
    float2 T[8];
#pragma unroll
    for (int p = 0; p < 8; ++p) {
        __half2 h = __ldcs(reinterpret_cast<const __half2*>(&g_t[(size_t)p * NT + i2]));
        T[p] = __half22float2(h);
    }
    int nu = (int)(i2 & 511);
    const float4* bias4 = reinterpret_cast<const float4*>(bias);
    float4* out4 = reinterpret_cast<float4*>(out);
#pragma unroll
    for (int j = 0; j < 2; ++j) {
        float t0 = (j ? T[0].y : T[0].x), t1 = (j ? T[1].y : T[1].x);
        float t2 = (j ? T[2].y : T[2].x), t3 = (j ? T[3].y : T[3].x);
        float t4 = (j ? T[4].y : T[4].x), t5 = (j ? T[5].y : T[5].x);
        float t6 = (j ? T[6].y : T[6].x), t7 = (j ? T[7].y : T[7].x);
        float s1 = t4 + t5, s2 = t6 + t7;
        float d1 = t4 - t5, d2 = t6 - t7;
        float4 b = bias4[nu + j];
        float4 o;
        o.x =  t1 + s1 + s2 + b.x;
        o.y =  t0 + s1 - s2 + b.y;
        o.z =  t2 - d1 + d2 + b.z;
        o.w = -t3 - d1 - d2 + b.w;
        __stcs(&out4[i2 + j], o);
    }
}

// ---------------- launch ----------------
extern "C" void kernel_launch(void* const* d_in, const int* in_sizes, int n_in,
                              void* d_out, int out_size) {
    (void)in_sizes; (void)n_in; (void)out_size;
    const float* input  = (const float*)d_in[0];
    const float* weight = (const float*)d_in[1];
    const float* bias   = (const float*)d_in[2];
    float* out = (float*)d_out;

    cudaFuncSetAttribute(qprod_gemm, cudaFuncAttributeMaxDynamicSharedMemorySize, SMEM_TOTAL);

    prep_kernel<<<XC_BLOCKS + 256, 256>>>(input, weight);
    qprod_gemm<<<dim3(XN / BN, N_ROWS / BM, NPROD), THREADS, SMEM_TOTAL>>>();
    combine_kernel<<<(unsigned)((NT / 2 + 255) / 256), 256>>>(bias, out);
}

// round 15
// speedup vs baseline: 1.1473x; 1.0021x over previous
#include <cuda_runtime.h>
#include <cuda_fp16.h>
#include <cstdint>

#define N_ROWS 8192
#define IN_F   2048
#define OUT_F  2048
#define XN     512
#define NPROD  8

static constexpr size_t NT = (size_t)N_ROWS * XN;

// ---------------- static device scratch ----------------
__device__ __half g_xc[NPROD * NT];          // 8 X-combos [8192 x 512] fp16 (64 MB)
__device__ __half g_wt[NPROD * XN * XN];     // 8 W-combos [512 x 512] fp16, [nu][kappa]
__device__ __half g_t [NPROD * NT];          // 8 products [8192 x 512] fp16 (64 MB)

// ---------------- fused prep: X combos (blocks 0..8191) + W combos (8192..8447)
#define XC_BLOCKS 8192

__global__ void prep_kernel(const float* __restrict__ in, const float* __restrict__ w) {
    __shared__ __half tile[NPROD][32][33];
    const int tid = threadIdx.x;
    if (blockIdx.x < XC_BLOCKS) {
        // ---- X combos: 2 elements per thread, half2 stores ----
        size_t i = (size_t)blockIdx.x * blockDim.x + tid;   // pair index
        if (i >= NT / 2) return;
        size_t i2 = i * 2;
        float4 v0 = reinterpret_cast<const float4*>(in)[i2];
        float4 v1 = reinterpret_cast<const float4*>(in)[i2 + 1];
#define PUT(p, e0, e1) \
        *reinterpret_cast<__half2*>(&g_xc[(size_t)(p) * NT + i2]) = __floats2half2_rn(e0, e1)
        PUT(0, v0.x + v0.y, v1.x + v1.y);
        PUT(1, v0.z - v0.w, v1.z - v1.w);
        PUT(2, v0.z + v0.w, v1.z + v1.w);
        PUT(3, v0.x - v0.y, v1.x - v1.y);
        PUT(4, v0.y + v0.z, v1.y + v1.z);
        PUT(5, v0.y - v0.z, v1.y - v1.z);
        PUT(6, v0.x - v0.w, v1.x - v1.w);
        PUT(7, v0.x + v0.w, v1.x + v1.w);
#undef PUT
    } else {
        // ---- W combos: 32x32 transpose tiles ----
        const int bid = blockIdx.x - XC_BLOCKS;       // 0..255
        const int kap0 = (bid >> 4) * 32;
        const int nu0  = (bid & 15) * 32;
        for (int p = 0; p < 4; ++p) {
            int r = p * 8 + (tid >> 5);
            int cnu = tid & 31;
            const float* wr = w + (size_t)(kap0 + r) * OUT_F + nu0 + cnu;
            float b0 = wr[0], b1 = wr[512], b2 = wr[1024], b3 = wr[1536];
            tile[0][r][cnu] = __float2half_rn(b0 - b1);
            tile[1][r][cnu] = __float2half_rn(b2 - b3);
            tile[2][r][cnu] = __float2half_rn(b0 + b1);
            tile[3][r][cnu] = __float2half_rn(b2 + b3);
            tile[4][r][cnu] = __float2half_rn(0.5f * (b1 + b3));
            tile[5][r][cnu] = __float2half_rn(0.5f * (b1 - b3));
            tile[6][r][cnu] = __float2half_rn(0.5f * (b0 - b2));
            tile[7][r][cnu] = __float2half_rn(0.5f * (b0 + b2));
        }
        __syncthreads();
        for (int p = 0; p < 4; ++p) {
            int rnu = p * 8 + (tid >> 5);
            int ck  = tid & 31;
#pragma unroll
            for (int i = 0; i < NPROD; ++i) {
                g_wt[(size_t)i * XN * XN + (size_t)(nu0 + rnu) * XN + kap0 + ck] = tile[i][ck][rnu];
            }
        }
    }
}

// ---------------- PTX helpers ----------------
__device__ __forceinline__ uint32_t smem_u32(const void* p) {
    uint32_t a;
    asm("{ .reg .u64 t; cvta.to.shared.u64 t, %1; cvt.u32.u64 %0, t; }" : "=r"(a) : "l"(p));
    return a;
}

#define CP_ASYNC16(dst, src) \
    asm volatile("cp.async.cg.shared.global [%0], [%1], 16;" :: "r"(dst), "l"(src))
#define CP_COMMIT() asm volatile("cp.async.commit_group;")
#define CP_WAIT(n)  asm volatile("cp.async.wait_group %0;" :: "n"(n))

__device__ __forceinline__ void ldsm_x4(uint32_t& r0, uint32_t& r1, uint32_t& r2, uint32_t& r3,
                                        uint32_t addr) {
    asm volatile("ldmatrix.sync.aligned.m8n8.x4.shared.b16 {%0,%1,%2,%3}, [%4];"
                 : "=r"(r0), "=r"(r1), "=r"(r2), "=r"(r3) : "r"(addr));
}

__device__ __forceinline__ void hmma(float* c, const uint32_t* a, uint32_t b0, uint32_t b1) {
    asm volatile(
        "mma.sync.aligned.m16n8k16.row.col.f32.f16.f16.f32 "
        "{%0,%1,%2,%3}, {%4,%5,%6,%7}, {%8,%9}, {%0,%1,%2,%3};"
        : "+f"(c[0]), "+f"(c[1]), "+f"(c[2]), "+f"(c[3])
        : "r"(a[0]), "r"(a[1]), "r"(a[2]), "r"(a[3]), "r"(b0), "r"(b1));
}

// ---------------- batched GEMM: t_z = XC_z [8192x512] @ WT_z [512x512]^T ----------------
#define BM 128
#define BN 128
#define BK 64
#define STAGES 3
#define THREADS 256
#define KTILES (XN / BK)      // 8

static constexpr int CHUNK_B = BM * 32 * 2;
static constexpr int OP_B    = 2 * CHUNK_B;
static constexpr int STAGE_B = 2 * OP_B;
static constexpr int SMEM_TOTAL = STAGES * STAGE_B;  // 96 KB

__global__ void __launch_bounds__(THREADS, 2) qprod_gemm()
{
    extern __shared__ char smem[];
    const uint32_t sbase = smem_u32(smem);
    const int tid  = threadIdx.x;
    const int wid  = tid >> 5;
    const int lane = tid & 31;
    const int warp_m = wid & 3;
    const int warp_n = wid >> 2;
    const int m0 = blockIdx.y * BM;
    const int n0 = blockIdx.x * BN;
    const int z  = blockIdx.z;

    const __half* gA = g_xc + (size_t)z * NT + (size_t)m0 * XN;
    const __half* gB = g_wt + (size_t)z * XN * XN + (size_t)n0 * XN;
    __half* gT = g_t + (size_t)z * NT;

    const int lr = tid >> 2;
    const int lc = tid & 3;
    const uint32_t dst_off = lr * 64 + ((lc ^ ((lr >> 1) & 3)) << 4);
    const size_t src_off = (size_t)lr * XN + lc * 8;

    const int g = lane >> 3, r = lane & 7;
    uint32_t a_row[2], a_sw[2];
    const int a_gbit = g >> 1;
#pragma unroll
    for (int mt = 0; mt < 2; ++mt) {
        int row = warp_m * 32 + mt * 16 + (g & 1) * 8 + r;
        a_row[mt] = row * 64;
        a_sw[mt]  = (row >> 1) & 3;
    }
    uint32_t b_row[4], b_sw[4];
    const int b_gbit = g & 1;
#pragma unroll
    for (int np = 0; np < 4; ++np) {
        int row = warp_n * 64 + np * 16 + (g >> 1) * 8 + r;
        b_row[np] = row * 64;
        b_sw[np]  = (row >> 1) & 3;
    }

    float acc[2][8][4];
#pragma unroll
    for (int mt = 0; mt < 2; ++mt)
#pragma unroll
        for (int nt = 0; nt < 8; ++nt)
#pragma unroll
            for (int e = 0; e < 4; ++e) acc[mt][nt][e] = 0.0f;

    int slot_of[KTILES + STAGES];
#pragma unroll
    for (int s = 0; s < KTILES + STAGES; ++s) slot_of[s] = s % STAGES;

    auto load_stage = [&](int s) {
        const int kc = s * BK;
        const uint32_t sb = sbase + slot_of[s] * STAGE_B;
        {
            const __half* asrc = gA + kc + src_off;
            const __half* bsrc = gB + kc + src_off;
#pragma unroll
            for (int c = 0; c < 2; ++c) {
                uint32_t da = sb + c * CHUNK_B + dst_off;
                uint32_t db = sb + OP_B + c * CHUNK_B + dst_off;
                CP_ASYNC16(da,        asrc + c * 32);
                CP_ASYNC16(da + 4096, asrc + c * 32 + (size_t)64 * XN);
                CP_ASYNC16(db,        bsrc + c * 32);
                CP_ASYNC16(db + 4096, bsrc + c * 32 + (size_t)64 * XN);
            }
        }
    };

    load_stage(0); CP_COMMIT();
    load_stage(1); CP_COMMIT();

    for (int s = 0; s < KTILES; ++s) {
        CP_WAIT(1);
        __syncthreads();
        if (s + 2 < KTILES) load_stage(s + 2);
        CP_COMMIT();

        const uint32_t sb = sbase + slot_of[s] * STAGE_B;
#pragma unroll
        for (int sk = 0; sk < 4; ++sk) {
            const uint32_t abase = sb + (sk >> 1) * CHUNK_B;
            const uint32_t bbase = sb + OP_B + (sk >> 1) * CHUNK_B;
            const uint32_t ca = (uint32_t)(2 * (sk & 1) + a_gbit);
            const uint32_t cb = (uint32_t)(2 * (sk & 1) + b_gbit);
            uint32_t ah[2][4], bh[4][4];
#pragma unroll
            for (int mt = 0; mt < 2; ++mt) {
                uint32_t off = a_row[mt] + ((ca ^ a_sw[mt]) << 4);
                ldsm_x4(ah[mt][0], ah[mt][1], ah[mt][2], ah[mt][3], abase + off);
            }
#pragma unroll
            for (int np = 0; np < 4; ++np) {
                uint32_t off = b_row[np] + ((cb ^ b_sw[np]) << 4);
                ldsm_x4(bh[np][0], bh[np][1], bh[np][2], bh[np][3], bbase + off);
            }
#pragma unroll
            for (int mt = 0; mt < 2; ++mt) {
#pragma unroll
                for (int nt = 0; nt < 8; ++nt) {
                    const int np = nt >> 1, sel = (nt & 1) * 2;
                    hmma(acc[mt][nt], ah[mt], bh[np][sel], bh[np][sel + 1]);
                }
            }
        }
    }

    // ---- epilogue: store t (fp16, pitch 512; normal stores keep g_t warm in L2)
#pragma unroll
    for (int mt = 0; mt < 2; ++mt) {
        int row = m0 + warp_m * 32 + mt * 16 + (lane >> 2);
#pragma unroll
        for (int nt = 0; nt < 8; ++nt) {
            int col = n0 + warp_n * 64 + nt * 8 + (lane & 3) * 2;
            *reinterpret_cast<__half2*>(gT + (size_t)row * XN + col) =
                __floats2half2_rn(acc[mt][nt][0], acc[mt][nt][1]);
            *reinterpret_cast<__half2*>(gT + (size_t)(row + 8) * XN + col) =
                __floats2half2_rn(acc[mt][nt][2], acc[mt][nt][3]);
        }
    }
}

// ---------------- combine: R12 shape; plain loads (L2-warm g_t), streamed stores
// O0 = T1 + (T4+T5) + (T6+T7)
// O1 = T0 + (T4+T5) - (T6+T7)
// O2 = T2 - (T4-T5) + (T6-T7)
// O3 = -T3 - (T4-T5) - (T6-T7)
__global__ void combine_kernel(const float* __restrict__ bias, float* __restrict__ out) {
    size_t i = (size_t)blockIdx.x * blockDim.x + threadIdx.x;   // pair index
    if (i >= NT / 2) return;
    size_t i2 = i * 2;
    float2 T[8];
#pragma unroll
    for (int p = 0; p < 8; ++p) {
        __half2 h = *reinterpret_cast<const __half2*>(&g_t[(size_t)p * NT + i2]);
        T[p] = __half22float2(h);
    }
    int nu = (int)(i2 & 511);
    const float4* bias4 = reinterpret_cast<const float4*>(bias);
    float4* out4 = reinterpret_cast<float4*>(out);
#pragma unroll
    for (int j = 0; j < 2; ++j) {
        float t0 = (j ? T[0].y : T[0].x), t1 = (j ? T[1].y : T[1].x);
        float t2 = (j ? T[2].y : T[2].x), t3 = (j ? T[3].y : T[3].x);
        float t4 = (j ? T[4].y : T[4].x), t5 = (j ? T[5].y : T[5].x);
        float t6 = (j ? T[6].y : T[6].x), t7 = (j ? T[7].y : T[7].x);
        float s1 = t4 + t5, s2 = t6 + t7;
        float d1 = t4 - t5, d2 = t6 - t7;
        float4 b = bias4[nu + j];
        float4 o;
        o.x =  t1 + s1 + s2 + b.x;
        o.y =  t0 + s1 - s2 + b.y;
        o.z =  t2 - d1 + d2 + b.z;
        o.w = -t3 - d1 - d2 + b.w;
        __stcs(&out4[i2 + j], o);
    }
}

// ---------------- launch ----------------
extern "C" void kernel_launch(void* const* d_in, const int* in_sizes, int n_in,
                              void* d_out, int out_size) {
    (void)in_sizes; (void)n_in; (void)out_size;
    const float* input  = (const float*)d_in[0];
    const float* weight = (const float*)d_in[1];
    const float* bias   = (const float*)d_in[2];
    float* out = (float*)d_out;

    cudaFuncSetAttribute(qprod_gemm, cudaFuncAttributeMaxDynamicSharedMemorySize, SMEM_TOTAL);

    prep_kernel<<<XC_BLOCKS + 256, 256>>>(input, weight);
    qprod_gemm<<<dim3(XN / BN, N_ROWS / BM, NPROD), THREADS, SMEM_TOTAL>>>();
    combine_kernel<<<(unsigned)((NT / 2 + 255) / 256), 256>>>(bias, out);
}